// round 1
// baseline (speedup 1.0000x reference)
#include <cuda_runtime.h>
#include <math.h>

#define BATCH 4
#define SLEN  2048
#define HID   896
#define NH    14
#define NKV   2
#define HD    64
#define NREP  (NH / NKV)

// ---------------- scratch (static device arrays; no allocation) ----------------
__device__ float g_Q[(size_t)BATCH * NH * SLEN * HD];    // [b][h][s][d]
__device__ float g_K[(size_t)BATCH * NKV * SLEN * HD];   // [b][kh][s][d]
__device__ float g_V[(size_t)BATCH * NKV * SLEN * HD];   // [b][kh][s][d]
__device__ float g_attn[(size_t)BATCH * SLEN * NH * HD]; // [b][s][h*HD+d]
__device__ float g_invf[HD / 2];

// ---------------- inv_freq init (fp64, 32 threads) ----------------
__global__ void init_invf_kernel() {
    int i = threadIdx.x;
    if (i < HD / 2) {
        g_invf[i] = (float)pow(1.0e6, -(double)i / 32.0);
    }
}

// ---------------- GEMM: C = A[M,K] * B[N,K]^T (+bias), NT form ----------------
// BM=BN=128, BK=16, 256 threads, 8x8 per thread.
// SCATTER=1: epilogue scatters into g_Q/g_K/g_V (head-major) chosen by `which`.
// A_ATTN=1: A is g_attn (ignore Ain param).
#define GBM 128
#define GBN 128
#define GBK 16

template <int SCATTER, int A_ATTN>
__global__ __launch_bounds__(256, 2)
void gemm_nt(const float* __restrict__ Ain, const float* __restrict__ B,
             const float* __restrict__ bias, float* __restrict__ Cout,
             int M, int N, int K, int which)
{
    __shared__ float As[GBK][GBM + 4];  // transposed: [k][m]
    __shared__ float Bs[GBK][GBN + 4];  // transposed: [k][n]

    const float* A = A_ATTN ? g_attn : Ain;

    const int tid = threadIdx.x;
    const int m0  = blockIdx.y * GBM;
    const int n0  = blockIdx.x * GBN;

    const float* Ablk = A + (size_t)m0 * K;
    const float* Bblk = B + (size_t)n0 * K;

    const int lr = tid >> 2;          // 0..63
    const int lc = (tid & 3) << 2;    // 0,4,8,12

    float4 aR0, aR1, bR0, bR1;
    aR0 = *(const float4*)(Ablk + (size_t)lr * K + lc);
    aR1 = *(const float4*)(Ablk + (size_t)(lr + 64) * K + lc);
    bR0 = *(const float4*)(Bblk + (size_t)lr * K + lc);
    bR1 = *(const float4*)(Bblk + (size_t)(lr + 64) * K + lc);

    float acc[8][8];
#pragma unroll
    for (int i = 0; i < 8; ++i)
#pragma unroll
        for (int j = 0; j < 8; ++j) acc[i][j] = 0.0f;

    const int ty = tid >> 4;   // 0..15
    const int tx = tid & 15;   // 0..15

    const int nt = K / GBK;
    for (int kt = 0; kt < nt; ++kt) {
        // stage registers -> smem (transposed)
        {
            const float* a0 = (const float*)&aR0;
            const float* a1 = (const float*)&aR1;
            const float* b0 = (const float*)&bR0;
            const float* b1 = (const float*)&bR1;
#pragma unroll
            for (int j = 0; j < 4; ++j) {
                As[lc + j][lr]      = a0[j];
                As[lc + j][lr + 64] = a1[j];
                Bs[lc + j][lr]      = b0[j];
                Bs[lc + j][lr + 64] = b1[j];
            }
        }
        __syncthreads();

        if (kt + 1 < nt) {
            const int ko = (kt + 1) * GBK + lc;
            aR0 = *(const float4*)(Ablk + (size_t)lr * K + ko);
            aR1 = *(const float4*)(Ablk + (size_t)(lr + 64) * K + ko);
            bR0 = *(const float4*)(Bblk + (size_t)lr * K + ko);
            bR1 = *(const float4*)(Bblk + (size_t)(lr + 64) * K + ko);
        }

#pragma unroll
        for (int k = 0; k < GBK; ++k) {
            float af[8], bf[8];
            *(float4*)&af[0] = *(const float4*)&As[k][ty * 8];
            *(float4*)&af[4] = *(const float4*)&As[k][ty * 8 + 4];
            *(float4*)&bf[0] = *(const float4*)&Bs[k][tx * 8];
            *(float4*)&bf[4] = *(const float4*)&Bs[k][tx * 8 + 4];
#pragma unroll
            for (int i = 0; i < 8; ++i)
#pragma unroll
                for (int j = 0; j < 8; ++j)
                    acc[i][j] += af[i] * bf[j];
        }
        __syncthreads();
    }

    const int gcol = n0 + tx * 8;  // 8 consecutive cols; never crosses a 64-col head
    if (SCATTER) {
        float bvals[8];
#pragma unroll
        for (int j = 0; j < 8; ++j) bvals[j] = bias[gcol + j];

        float* buf;
        int nh;
        if (which == 0)      { buf = g_Q; nh = NH;  }
        else if (which == 1) { buf = g_K; nh = NKV; }
        else                 { buf = g_V; nh = NKV; }
        const int h = gcol / HD;
        const int d = gcol % HD;

#pragma unroll
        for (int i = 0; i < 8; ++i) {
            const int m = m0 + ty * 8 + i;
            const int b = m >> 11;          // / SLEN
            const int s = m & (SLEN - 1);
            float* dst = buf + (((size_t)(b * nh + h)) * SLEN + s) * HD + d;
            float4 v0, v1;
            v0.x = acc[i][0] + bvals[0]; v0.y = acc[i][1] + bvals[1];
            v0.z = acc[i][2] + bvals[2]; v0.w = acc[i][3] + bvals[3];
            v1.x = acc[i][4] + bvals[4]; v1.y = acc[i][5] + bvals[5];
            v1.z = acc[i][6] + bvals[6]; v1.w = acc[i][7] + bvals[7];
            *(float4*)dst       = v0;
            *(float4*)(dst + 4) = v1;
        }
    } else {
#pragma unroll
        for (int i = 0; i < 8; ++i) {
            const int m = m0 + ty * 8 + i;
            float* dst = Cout + (size_t)m * N + gcol;
            float4 v0, v1;
            v0.x = acc[i][0]; v0.y = acc[i][1]; v0.z = acc[i][2]; v0.w = acc[i][3];
            v1.x = acc[i][4]; v1.y = acc[i][5]; v1.z = acc[i][6]; v1.w = acc[i][7];
            *(float4*)dst       = v0;
            *(float4*)(dst + 4) = v1;
        }
    }
}

// ---------------- RoPE (in-place on g_Q, g_K) ----------------
__global__ void rope_kernel(const int* __restrict__ pos_ids) {
    const int QROWS = BATCH * NH * SLEN;  // 114688
    const int idx  = blockIdx.x * blockDim.x + threadIdx.x;
    const int pair = idx & 31;
    const int row  = idx >> 5;

    float* base;
    if (row < QROWS) base = g_Q + (size_t)row * HD;
    else             base = g_K + (size_t)(row - QROWS) * HD;

    const int s   = row & (SLEN - 1);
    const float p = (float)pos_ids[s];
    const float inv = g_invf[pair];
    const float ang = p * inv;
    float sn, cs;
    sincosf(ang, &sn, &cs);
    const float x1 = base[pair];
    const float x2 = base[pair + 32];
    base[pair]      = x1 * cs - x2 * sn;
    base[pair + 32] = x2 * cs + x1 * sn;
}

// ---------------- Flash attention (causal, GQA) ----------------
// BM=128 queries, BN=64 keys, HD=64. 256 threads: (ty 0..15) x (tx 0..15).
// S tile: thread owns 8 rows x 4 key-cols; O: 8 rows x 4 d-cols.
#define FBM 128
#define FBN 64
#define FLASH_SMEM_FLOATS (64 * 132 + 64 * 68 + 64 * 68 + 128 * 68)
#define FLASH_SMEM_BYTES  (FLASH_SMEM_FLOATS * 4)

__global__ __launch_bounds__(256, 2)
void flash_kernel() {
    extern __shared__ float sm[];
    float* Qs = sm;                      // [d=64][m=128+4pad=132]
    float* Ks = Qs + 64 * 132;           // [d=64][n=64+4pad=68]
    float* Vs = Ks + 64 * 68;            // [n=64][d=64+4pad=68]
    float* Ps = Vs + 64 * 68;            // [m=128][n=64+4pad=68]

    const int tid = threadIdx.x;
    const int blk = blockIdx.x;   // q tile 0..15
    const int h   = blockIdx.y;   // 0..13
    const int b   = blockIdx.z;   // 0..3
    const int qi0 = blk * FBM;
    const int kh  = h / NREP;

    const float* Qg  = g_Q + (((size_t)(b * NH + h)) * SLEN + qi0) * HD;
    const float* Kg0 = g_K + ((size_t)(b * NKV + kh)) * SLEN * HD;
    const float* Vg0 = g_V + ((size_t)(b * NKV + kh)) * SLEN * HD;

    // load Q tile transposed -> Qs[d][m]
#pragma unroll
    for (int it = 0; it < 8; ++it) {
        const int idx = tid + it * 256;      // float4 index, 0..2047
        const int r   = idx >> 4;            // 0..127
        const int c4  = (idx & 15) << 2;     // 0..60
        const float4 v = *(const float4*)(Qg + (size_t)r * HD + c4);
        Qs[(c4 + 0) * 132 + r] = v.x;
        Qs[(c4 + 1) * 132 + r] = v.y;
        Qs[(c4 + 2) * 132 + r] = v.z;
        Qs[(c4 + 3) * 132 + r] = v.w;
    }

    const int ty = tid >> 4, tx = tid & 15;
    const int m0 = ty * 8;
    const int n0 = tx * 4;   // also the d-col base for O

    float o[8][4];
    float l[8], mx[8];
#pragma unroll
    for (int i = 0; i < 8; ++i) {
        l[i] = 0.0f; mx[i] = -1e30f;
#pragma unroll
        for (int c = 0; c < 4; ++c) o[i][c] = 0.0f;
    }

    const float scale = 0.125f;  // 1/sqrt(64)
    const int jmax = 2 * blk + 1;

    for (int j = 0; j <= jmax; ++j) {
        const int k0 = j * FBN;
        __syncthreads();  // previous PV must finish before K/V/P reuse

        // load K transposed -> Ks[d][n]; V direct -> Vs[n][d]
#pragma unroll
        for (int it = 0; it < 4; ++it) {
            const int idx = tid + it * 256;   // 0..1023
            const int r   = idx >> 4;         // 0..63
            const int c4  = (idx & 15) << 2;
            const float4 kv = *(const float4*)(Kg0 + (size_t)(k0 + r) * HD + c4);
            Ks[(c4 + 0) * 68 + r] = kv.x;
            Ks[(c4 + 1) * 68 + r] = kv.y;
            Ks[(c4 + 2) * 68 + r] = kv.z;
            Ks[(c4 + 3) * 68 + r] = kv.w;
            const float4 vv = *(const float4*)(Vg0 + (size_t)(k0 + r) * HD + c4);
            *(float4*)&Vs[r * 68 + c4] = vv;
        }
        __syncthreads();

        // S = Q * K^T  (8x4 per thread)
        float sacc[8][4];
#pragma unroll
        for (int i = 0; i < 8; ++i)
#pragma unroll
            for (int c = 0; c < 4; ++c) sacc[i][c] = 0.0f;

#pragma unroll 8
        for (int d = 0; d < 64; ++d) {
            float af[8], bf[4];
            *(float4*)&af[0] = *(const float4*)&Qs[d * 132 + m0];
            *(float4*)&af[4] = *(const float4*)&Qs[d * 132 + m0 + 4];
            *(float4*)&bf[0] = *(const float4*)&Ks[d * 68 + n0];
#pragma unroll
            for (int i = 0; i < 8; ++i)
#pragma unroll
                for (int c = 0; c < 4; ++c)
                    sacc[i][c] += af[i] * bf[c];
        }

        const bool need_mask = (k0 + FBN - 1 > qi0);
#pragma unroll
        for (int i = 0; i < 8; ++i) {
#pragma unroll
            for (int c = 0; c < 4; ++c) {
                float v = sacc[i][c] * scale;
                if (need_mask && (k0 + n0 + c > qi0 + m0 + i)) v = -1e30f;
                sacc[i][c] = v;
            }
        }

        // online softmax per row (row spread over 16 lanes sharing ty)
#pragma unroll
        for (int i = 0; i < 8; ++i) {
            float rm = fmaxf(fmaxf(sacc[i][0], sacc[i][1]),
                             fmaxf(sacc[i][2], sacc[i][3]));
            rm = fmaxf(rm, __shfl_xor_sync(0xffffffffu, rm, 1));
            rm = fmaxf(rm, __shfl_xor_sync(0xffffffffu, rm, 2));
            rm = fmaxf(rm, __shfl_xor_sync(0xffffffffu, rm, 4));
            rm = fmaxf(rm, __shfl_xor_sync(0xffffffffu, rm, 8));

            const float mnew = fmaxf(mx[i], rm);
            const float corr = __expf(mx[i] - mnew);
            mx[i] = mnew;

            float rs = 0.0f;
#pragma unroll
            for (int c = 0; c < 4; ++c) {
                const float pv = __expf(sacc[i][c] - mnew);
                sacc[i][c] = pv;
                rs += pv;
            }
            rs += __shfl_xor_sync(0xffffffffu, rs, 1);
            rs += __shfl_xor_sync(0xffffffffu, rs, 2);
            rs += __shfl_xor_sync(0xffffffffu, rs, 4);
            rs += __shfl_xor_sync(0xffffffffu, rs, 8);

            l[i] = l[i] * corr + rs;
#pragma unroll
            for (int c = 0; c < 4; ++c) o[i][c] *= corr;

            // stage P row chunk (vectorized, conflict-free)
            float4 pr;
            pr.x = sacc[i][0]; pr.y = sacc[i][1]; pr.z = sacc[i][2]; pr.w = sacc[i][3];
            *(float4*)&Ps[(m0 + i) * 68 + n0] = pr;
        }
        __syncthreads();

        // O += P * V  (8 rows x 4 d-cols)
#pragma unroll 8
        for (int kk = 0; kk < 64; ++kk) {
            const float4 v = *(const float4*)&Vs[kk * 68 + n0];
#pragma unroll
            for (int i = 0; i < 8; ++i) {
                const float p = Ps[(m0 + i) * 68 + kk];
                o[i][0] += p * v.x;
                o[i][1] += p * v.y;
                o[i][2] += p * v.z;
                o[i][3] += p * v.w;
            }
        }
    }

    // write O / l  ->  g_attn[b][s][h*HD + d]
#pragma unroll
    for (int i = 0; i < 8; ++i) {
        const float invl = 1.0f / l[i];
        const int srow = qi0 + m0 + i;
        float* dst = g_attn + ((size_t)(b * SLEN) + srow) * (NH * HD) + h * HD + n0;
        float4 r;
        r.x = o[i][0] * invl; r.y = o[i][1] * invl;
        r.z = o[i][2] * invl; r.w = o[i][3] * invl;
        *(float4*)dst = r;
    }
}

// ---------------- launch ----------------
extern "C" void kernel_launch(void* const* d_in, const int* in_sizes, int n_in,
                              void* d_out, int out_size) {
    const float* hs  = (const float*)d_in[0];
    const int*   pos = (const int*)d_in[1];
    const float* Wq  = (const float*)d_in[2];
    const float* bq  = (const float*)d_in[3];
    const float* Wk  = (const float*)d_in[4];
    const float* bk  = (const float*)d_in[5];
    const float* Wv  = (const float*)d_in[6];
    const float* bv  = (const float*)d_in[7];
    const float* Wo  = (const float*)d_in[8];
    float* out = (float*)d_out;

    (void)in_sizes; (void)n_in; (void)out_size;

    cudaFuncSetAttribute(flash_kernel,
                         cudaFuncAttributeMaxDynamicSharedMemorySize,
                         FLASH_SMEM_BYTES);

    const int M = BATCH * SLEN;  // 8192
    dim3 thr(256);

    // QKV projections (scatter epilogue into head-major buffers, +bias)
    gemm_nt<1, 0><<<dim3(HID / GBN, M / GBM), thr>>>(hs, Wq, bq, nullptr, M, NH * HD, HID, 0);
    gemm_nt<1, 0><<<dim3(1,        M / GBM), thr>>>(hs, Wk, bk, nullptr, M, NKV * HD, HID, 1);
    gemm_nt<1, 0><<<dim3(1,        M / GBM), thr>>>(hs, Wv, bv, nullptr, M, NKV * HD, HID, 2);

    // RoPE
    init_invf_kernel<<<1, 32>>>();
    {
        const int qrows = BATCH * NH * SLEN;
        const int krows = BATCH * NKV * SLEN;
        const int total = (qrows + krows) * (HD / 2);
        rope_kernel<<<total / 256, 256>>>(pos);
    }

    // Flash attention
    flash_kernel<<<dim3(SLEN / FBM, NH, BATCH), thr, FLASH_SMEM_BYTES>>>();

    // Output projection -> d_out
    gemm_nt<0, 1><<<dim3(HID / GBN, M / GBM), thr>>>(nullptr, Wo, nullptr, out, M, HID, HID, 0);
}

// round 3
// speedup vs baseline: 1.1134x; 1.1134x over previous
#include <cuda_runtime.h>
#include <math.h>

#define BATCH 4
#define SLEN  2048
#define HID   896
#define NH    14
#define NKV   2
#define HD    64
#define NREP  (NH / NKV)

typedef unsigned long long u64;

// packed fp32x2 helpers (SASS FFMA2 path — only reachable via PTX)
#define FFMA2(acc, a, b) asm("fma.rn.f32x2 %0, %1, %2, %0;" : "+l"(acc) : "l"(a), "l"(b))
#define FMUL2(d, a, b)   asm("mul.rn.f32x2 %0, %1, %2;" : "=l"(d) : "l"(a), "l"(b))
#define PACKDUP(d, x)    asm("mov.b64 %0, {%1, %1};" : "=l"(d) : "r"(x))
#define UNPACK2(lo, hi, v) asm("mov.b64 {%0, %1}, %2;" : "=r"(lo), "=r"(hi) : "l"(v))

// ---------------- scratch ----------------
__device__ float g_Q[(size_t)BATCH * NH * SLEN * HD];    // [b][h][s][d]
__device__ float g_K[(size_t)BATCH * NKV * SLEN * HD];   // [b][kh][s][d]
__device__ float g_V[(size_t)BATCH * NKV * SLEN * HD];   // [b][kh][s][d]
__device__ float g_attn[(size_t)BATCH * SLEN * NH * HD]; // [b][s][h*HD+d]
__device__ float g_invf[HD / 2];

__global__ void init_invf_kernel() {
    int i = threadIdx.x;
    if (i < HD / 2) g_invf[i] = (float)pow(1.0e6, -(double)i / 32.0);
}

// ---------------- GEMM: C = A[M,K] * B[N,K]^T (+bias) ----------------
#define GBM 128
#define GBN 128
#define GBK 16

template <int SCATTER, int A_ATTN>
__global__ __launch_bounds__(256, 2)
void gemm_nt(const float* __restrict__ Ain, const float* __restrict__ B,
             const float* __restrict__ bias, float* __restrict__ Cout,
             int M, int N, int K, int which)
{
    __shared__ float As[GBK][GBM + 4];
    __shared__ float Bs[GBK][GBN + 4];

    const float* A = A_ATTN ? g_attn : Ain;

    const int tid = threadIdx.x;
    const int m0  = blockIdx.y * GBM;
    const int n0  = blockIdx.x * GBN;

    const float* Ablk = A + (size_t)m0 * K;
    const float* Bblk = B + (size_t)n0 * K;

    const int lr = tid >> 2;
    const int lc = (tid & 3) << 2;

    float4 aR0, aR1, bR0, bR1;
    aR0 = *(const float4*)(Ablk + (size_t)lr * K + lc);
    aR1 = *(const float4*)(Ablk + (size_t)(lr + 64) * K + lc);
    bR0 = *(const float4*)(Bblk + (size_t)lr * K + lc);
    bR1 = *(const float4*)(Bblk + (size_t)(lr + 64) * K + lc);

    u64 acc2[8][4];
#pragma unroll
    for (int i = 0; i < 8; ++i)
#pragma unroll
        for (int j = 0; j < 4; ++j) acc2[i][j] = 0ULL;

    const int ty = tid >> 4;
    const int tx = tid & 15;

    const int nt = K / GBK;
    for (int kt = 0; kt < nt; ++kt) {
        {
            const float* a0 = (const float*)&aR0;
            const float* a1 = (const float*)&aR1;
            const float* b0 = (const float*)&bR0;
            const float* b1 = (const float*)&bR1;
#pragma unroll
            for (int j = 0; j < 4; ++j) {
                As[lc + j][lr]      = a0[j];
                As[lc + j][lr + 64] = a1[j];
                Bs[lc + j][lr]      = b0[j];
                Bs[lc + j][lr + 64] = b1[j];
            }
        }
        __syncthreads();

        if (kt + 1 < nt) {
            const int ko = (kt + 1) * GBK + lc;
            aR0 = *(const float4*)(Ablk + (size_t)lr * K + ko);
            aR1 = *(const float4*)(Ablk + (size_t)(lr + 64) * K + ko);
            bR0 = *(const float4*)(Bblk + (size_t)lr * K + ko);
            bR1 = *(const float4*)(Bblk + (size_t)(lr + 64) * K + ko);
        }

#pragma unroll
        for (int k = 0; k < GBK; ++k) {
            float af[8];
            *(float4*)&af[0] = *(const float4*)&As[k][ty * 8];
            *(float4*)&af[4] = *(const float4*)&As[k][ty * 8 + 4];
            const u64* bp = (const u64*)&Bs[k][tx * 8];
            u64 b2[4];
            b2[0] = bp[0]; b2[1] = bp[1]; b2[2] = bp[2]; b2[3] = bp[3];
#pragma unroll
            for (int i = 0; i < 8; ++i) {
                u64 a2;
                PACKDUP(a2, __float_as_uint(af[i]));
                FFMA2(acc2[i][0], a2, b2[0]);
                FFMA2(acc2[i][1], a2, b2[1]);
                FFMA2(acc2[i][2], a2, b2[2]);
                FFMA2(acc2[i][3], a2, b2[3]);
            }
        }
        __syncthreads();
    }

    // unpack accumulators
    float acc[8][8];
#pragma unroll
    for (int i = 0; i < 8; ++i)
#pragma unroll
        for (int j = 0; j < 4; ++j) {
            unsigned int lo, hi;
            UNPACK2(lo, hi, acc2[i][j]);
            acc[i][2 * j]     = __uint_as_float(lo);
            acc[i][2 * j + 1] = __uint_as_float(hi);
        }

    const int gcol = n0 + tx * 8;
    if (SCATTER) {
        float bvals[8];
#pragma unroll
        for (int j = 0; j < 8; ++j) bvals[j] = bias[gcol + j];

        float* buf;
        int nh;
        if (which == 0)      { buf = g_Q; nh = NH;  }
        else if (which == 1) { buf = g_K; nh = NKV; }
        else                 { buf = g_V; nh = NKV; }
        const int h = gcol / HD;
        const int d = gcol % HD;

#pragma unroll
        for (int i = 0; i < 8; ++i) {
            const int m = m0 + ty * 8 + i;
            const int b = m >> 11;
            const int s = m & (SLEN - 1);
            float* dst = buf + (((size_t)(b * nh + h)) * SLEN + s) * HD + d;
            float4 v0, v1;
            v0.x = acc[i][0] + bvals[0]; v0.y = acc[i][1] + bvals[1];
            v0.z = acc[i][2] + bvals[2]; v0.w = acc[i][3] + bvals[3];
            v1.x = acc[i][4] + bvals[4]; v1.y = acc[i][5] + bvals[5];
            v1.z = acc[i][6] + bvals[6]; v1.w = acc[i][7] + bvals[7];
            *(float4*)dst       = v0;
            *(float4*)(dst + 4) = v1;
        }
    } else {
#pragma unroll
        for (int i = 0; i < 8; ++i) {
            const int m = m0 + ty * 8 + i;
            float* dst = Cout + (size_t)m * N + gcol;
            float4 v0, v1;
            v0.x = acc[i][0]; v0.y = acc[i][1]; v0.z = acc[i][2]; v0.w = acc[i][3];
            v1.x = acc[i][4]; v1.y = acc[i][5]; v1.z = acc[i][6]; v1.w = acc[i][7];
            *(float4*)dst       = v0;
            *(float4*)(dst + 4) = v1;
        }
    }
}

// ---------------- RoPE ----------------
__global__ void rope_kernel(const int* __restrict__ pos_ids) {
    const int QROWS = BATCH * NH * SLEN;
    const int idx  = blockIdx.x * blockDim.x + threadIdx.x;
    const int pair = idx & 31;
    const int row  = idx >> 5;

    float* base;
    if (row < QROWS) base = g_Q + (size_t)row * HD;
    else             base = g_K + (size_t)(row - QROWS) * HD;

    const int s   = row & (SLEN - 1);
    const float p = (float)pos_ids[s];
    const float ang = p * g_invf[pair];
    float sn, cs;
    sincosf(ang, &sn, &cs);
    const float x1 = base[pair];
    const float x2 = base[pair + 32];
    base[pair]      = x1 * cs - x2 * sn;
    base[pair + 32] = x2 * cs + x1 * sn;
}

// ---------------- Flash attention (causal, GQA) ----------------
// BM=128 q, BN=128 k, HD=64. 256 threads: thread owns 8 q-rows x 8 k-cols of S,
// and 8 q-rows x 4 d-cols of O. All FMA loops packed f32x2.
#define FBM 128
#define FBN 128
#define QS_STRIDE 132
#define KS_STRIDE 132
#define VS_STRIDE 68
#define PS_STRIDE 132
#define FLASH_SMEM_FLOATS (64 * QS_STRIDE + 64 * KS_STRIDE + 128 * VS_STRIDE + 128 * PS_STRIDE)
#define FLASH_SMEM_BYTES  (FLASH_SMEM_FLOATS * 4)

__global__ __launch_bounds__(256, 1)
void flash_kernel() {
    extern __shared__ float sm[];
    float* Qs = sm;                          // [d=64][m=128] stride 132
    float* Ks = Qs + 64 * QS_STRIDE;         // [d=64][n=128] stride 132
    float* Vs = Ks + 64 * KS_STRIDE;         // [n=128][d=64] stride 68
    float* Ps = Vs + 128 * VS_STRIDE;        // [m=128][n=128] stride 132

    const int tid = threadIdx.x;
    const int blk = blockIdx.x;   // q tile 0..15
    const int h   = blockIdx.y;
    const int b   = blockIdx.z;
    const int qi0 = blk * FBM;
    const int kh  = h / NREP;

    const float* Qg  = g_Q + (((size_t)(b * NH + h)) * SLEN + qi0) * HD;
    const float* Kg0 = g_K + ((size_t)(b * NKV + kh)) * SLEN * HD;
    const float* Vg0 = g_V + ((size_t)(b * NKV + kh)) * SLEN * HD;

    // Q tile transposed -> Qs[d][m]
#pragma unroll
    for (int it = 0; it < 8; ++it) {
        const int idx = tid + it * 256;
        const int r   = idx >> 4;
        const int c4  = (idx & 15) << 2;
        const float4 v = *(const float4*)(Qg + (size_t)r * HD + c4);
        Qs[(c4 + 0) * QS_STRIDE + r] = v.x;
        Qs[(c4 + 1) * QS_STRIDE + r] = v.y;
        Qs[(c4 + 2) * QS_STRIDE + r] = v.z;
        Qs[(c4 + 3) * QS_STRIDE + r] = v.w;
    }

    const int ty = tid >> 4, tx = tid & 15;
    const int m0  = ty * 8;
    const int n0s = tx * 8;   // S cols
    const int n0v = tx * 4;   // O d-cols

    u64 o2[8][2];
    float l[8], mx[8];
#pragma unroll
    for (int i = 0; i < 8; ++i) {
        l[i] = 0.0f; mx[i] = -1e30f;
        o2[i][0] = 0ULL; o2[i][1] = 0ULL;
    }

    const float scale = 0.125f;
    const int jmax = blk;

    for (int j = 0; j <= jmax; ++j) {
        const int k0 = j * FBN;
        __syncthreads();

        // K transposed -> Ks[d][n]; V -> Vs[n][d]
#pragma unroll
        for (int it = 0; it < 8; ++it) {
            const int idx = tid + it * 256;      // 0..2047
            const int r   = idx >> 4;            // 0..127
            const int c4  = (idx & 15) << 2;
            const float4 kv = *(const float4*)(Kg0 + (size_t)(k0 + r) * HD + c4);
            Ks[(c4 + 0) * KS_STRIDE + r] = kv.x;
            Ks[(c4 + 1) * KS_STRIDE + r] = kv.y;
            Ks[(c4 + 2) * KS_STRIDE + r] = kv.z;
            Ks[(c4 + 3) * KS_STRIDE + r] = kv.w;
            const float4 vv = *(const float4*)(Vg0 + (size_t)(k0 + r) * HD + c4);
            *(float4*)&Vs[r * VS_STRIDE + c4] = vv;
        }
        __syncthreads();

        // S = Q*K^T (8x8 per thread, packed)
        u64 sacc2[8][4];
#pragma unroll
        for (int i = 0; i < 8; ++i)
#pragma unroll
            for (int c = 0; c < 4; ++c) sacc2[i][c] = 0ULL;

#pragma unroll 4
        for (int d = 0; d < 64; ++d) {
            float af[8];
            *(float4*)&af[0] = *(const float4*)&Qs[d * QS_STRIDE + m0];
            *(float4*)&af[4] = *(const float4*)&Qs[d * QS_STRIDE + m0 + 4];
            const u64* bp = (const u64*)&Ks[d * KS_STRIDE + n0s];
            u64 b2[4];
            b2[0] = bp[0]; b2[1] = bp[1]; b2[2] = bp[2]; b2[3] = bp[3];
#pragma unroll
            for (int i = 0; i < 8; ++i) {
                u64 a2;
                PACKDUP(a2, __float_as_uint(af[i]));
                FFMA2(sacc2[i][0], a2, b2[0]);
                FFMA2(sacc2[i][1], a2, b2[1]);
                FFMA2(sacc2[i][2], a2, b2[2]);
                FFMA2(sacc2[i][3], a2, b2[3]);
            }
        }

        const bool need_mask = (j == blk);

        // softmax per row + stage P
#pragma unroll
        for (int i = 0; i < 8; ++i) {
            float s[8];
#pragma unroll
            for (int c = 0; c < 4; ++c) {
                unsigned int lo, hi;
                UNPACK2(lo, hi, sacc2[i][c]);
                s[2 * c]     = __uint_as_float(lo) * scale;
                s[2 * c + 1] = __uint_as_float(hi) * scale;
            }
            if (need_mask) {
#pragma unroll
                for (int c = 0; c < 8; ++c)
                    if (k0 + n0s + c > qi0 + m0 + i) s[c] = -1e30f;
            }

            float rm = s[0];
#pragma unroll
            for (int c = 1; c < 8; ++c) rm = fmaxf(rm, s[c]);
            rm = fmaxf(rm, __shfl_xor_sync(0xffffffffu, rm, 1));
            rm = fmaxf(rm, __shfl_xor_sync(0xffffffffu, rm, 2));
            rm = fmaxf(rm, __shfl_xor_sync(0xffffffffu, rm, 4));
            rm = fmaxf(rm, __shfl_xor_sync(0xffffffffu, rm, 8));

            const float mnew = fmaxf(mx[i], rm);
            const float corr = __expf(mx[i] - mnew);
            mx[i] = mnew;

            float rs = 0.0f;
#pragma unroll
            for (int c = 0; c < 8; ++c) {
                s[c] = __expf(s[c] - mnew);
                rs += s[c];
            }
            rs += __shfl_xor_sync(0xffffffffu, rs, 1);
            rs += __shfl_xor_sync(0xffffffffu, rs, 2);
            rs += __shfl_xor_sync(0xffffffffu, rs, 4);
            rs += __shfl_xor_sync(0xffffffffu, rs, 8);

            l[i] = l[i] * corr + rs;

            u64 c2;
            PACKDUP(c2, __float_as_uint(corr));
            FMUL2(o2[i][0], o2[i][0], c2);
            FMUL2(o2[i][1], o2[i][1], c2);

            *(float4*)&Ps[(m0 + i) * PS_STRIDE + n0s]     = *(float4*)&s[0];
            *(float4*)&Ps[(m0 + i) * PS_STRIDE + n0s + 4] = *(float4*)&s[4];
        }
        __syncthreads();

        // O += P * V  (packed, 4 keys at a time)
#pragma unroll 2
        for (int kk4 = 0; kk4 < 32; ++kk4) {
            const int kk = kk4 * 4;
            u64 v2[4][2];
#pragma unroll
            for (int q = 0; q < 4; ++q) {
                const u64* vp = (const u64*)&Vs[(kk + q) * VS_STRIDE + n0v];
                v2[q][0] = vp[0];
                v2[q][1] = vp[1];
            }
#pragma unroll
            for (int i = 0; i < 8; ++i) {
                float4 p4 = *(const float4*)&Ps[(m0 + i) * PS_STRIDE + kk];
                u64 p2;
                PACKDUP(p2, __float_as_uint(p4.x));
                FFMA2(o2[i][0], p2, v2[0][0]);
                FFMA2(o2[i][1], p2, v2[0][1]);
                PACKDUP(p2, __float_as_uint(p4.y));
                FFMA2(o2[i][0], p2, v2[1][0]);
                FFMA2(o2[i][1], p2, v2[1][1]);
                PACKDUP(p2, __float_as_uint(p4.z));
                FFMA2(o2[i][0], p2, v2[2][0]);
                FFMA2(o2[i][1], p2, v2[2][1]);
                PACKDUP(p2, __float_as_uint(p4.w));
                FFMA2(o2[i][0], p2, v2[3][0]);
                FFMA2(o2[i][1], p2, v2[3][1]);
            }
        }
    }

    // write O -> g_attn[b][s][h*HD + d]
#pragma unroll
    for (int i = 0; i < 8; ++i) {
        const float invl = 1.0f / l[i];
        const int srow = qi0 + m0 + i;
        float* dst = g_attn + ((size_t)(b * SLEN) + srow) * (NH * HD) + h * HD + n0v;
        unsigned int lo, hi;
        float4 r;
        UNPACK2(lo, hi, o2[i][0]);
        r.x = __uint_as_float(lo) * invl; r.y = __uint_as_float(hi) * invl;
        UNPACK2(lo, hi, o2[i][1]);
        r.z = __uint_as_float(lo) * invl; r.w = __uint_as_float(hi) * invl;
        *(float4*)dst = r;
    }
}

// ---------------- launch ----------------
extern "C" void kernel_launch(void* const* d_in, const int* in_sizes, int n_in,
                              void* d_out, int out_size) {
    const float* hs  = (const float*)d_in[0];
    const int*   pos = (const int*)d_in[1];
    const float* Wq  = (const float*)d_in[2];
    const float* bq  = (const float*)d_in[3];
    const float* Wk  = (const float*)d_in[4];
    const float* bk  = (const float*)d_in[5];
    const float* Wv  = (const float*)d_in[6];
    const float* bv  = (const float*)d_in[7];
    const float* Wo  = (const float*)d_in[8];
    float* out = (float*)d_out;

    (void)in_sizes; (void)n_in; (void)out_size;

    cudaFuncSetAttribute(flash_kernel,
                         cudaFuncAttributeMaxDynamicSharedMemorySize,
                         FLASH_SMEM_BYTES);

    const int M = BATCH * SLEN;
    dim3 thr(256);

    init_invf_kernel<<<1, 32>>>();

    gemm_nt<1, 0><<<dim3(HID / GBN, M / GBM), thr>>>(hs, Wq, bq, nullptr, M, NH * HD, HID, 0);
    gemm_nt<1, 0><<<dim3(1,        M / GBM), thr>>>(hs, Wk, bk, nullptr, M, NKV * HD, HID, 1);
    gemm_nt<1, 0><<<dim3(1,        M / GBM), thr>>>(hs, Wv, bv, nullptr, M, NKV * HD, HID, 2);

    {
        const int qrows = BATCH * NH * SLEN;
        const int krows = BATCH * NKV * SLEN;
        const int total = (qrows + krows) * (HD / 2);
        rope_kernel<<<total / 256, 256>>>(pos);
    }

    flash_kernel<<<dim3(SLEN / FBM, NH, BATCH), thr, FLASH_SMEM_BYTES>>>();

    gemm_nt<0, 1><<<dim3(HID / GBN, M / GBM), thr>>>(nullptr, Wo, nullptr, out, M, HID, HID, 0);
}

// round 5
// speedup vs baseline: 1.6073x; 1.4435x over previous
#include <cuda_runtime.h>
#include <cuda_bf16.h>
#include <math.h>

#define BATCH 4
#define SLEN  2048
#define HID   896
#define NH    14
#define NKV   2
#define HD    64
#define NREP  (NH / NKV)

typedef unsigned long long u64;
typedef unsigned int u32;

// packed fp32x2 helpers (flash kernel)
#define FFMA2(acc, a, b) asm("fma.rn.f32x2 %0, %1, %2, %0;" : "+l"(acc) : "l"(a), "l"(b))
#define FMUL2(d, a, b)   asm("mul.rn.f32x2 %0, %1, %2;" : "=l"(d) : "l"(a), "l"(b))
#define PACKDUP(d, x)    asm("mov.b64 %0, {%1, %1};" : "=l"(d) : "r"(x))
#define UNPACK2(lo, hi, v) asm("mov.b64 {%0, %1}, %2;" : "=r"(lo), "=r"(hi) : "l"(v))

// ---------------- scratch ----------------
__device__ float g_Q[(size_t)BATCH * NH * SLEN * HD];    // [b][h][s][d]
__device__ float g_K[(size_t)BATCH * NKV * SLEN * HD];   // [b][kh][s][d]
__device__ float g_V[(size_t)BATCH * NKV * SLEN * HD];   // [b][kh][s][d]
__device__ float g_attn[(size_t)BATCH * SLEN * NH * HD]; // [b][s][h*HD+d]
__device__ float g_invf[HD / 2];

__global__ void init_invf_kernel() {
    int i = threadIdx.x;
    if (i < HD / 2) g_invf[i] = (float)pow(1.0e6, -(double)i / 32.0);
}

// ================= mma.sync helpers (sm_80+ baseline PTX) =================
__device__ __forceinline__ u32 smem_u32(const void* p) {
    u32 a;
    asm("{ .reg .u64 t; cvta.to.shared.u64 t, %1; cvt.u32.u64 %0, t; }" : "=r"(a) : "l"(p));
    return a;
}
__device__ __forceinline__ void mma16816(float* d, const u32* a, const u32* b) {
    asm volatile(
        "mma.sync.aligned.m16n8k16.row.col.f32.bf16.bf16.f32 "
        "{%0,%1,%2,%3}, {%4,%5,%6,%7}, {%8,%9}, {%0,%1,%2,%3};"
        : "+f"(d[0]), "+f"(d[1]), "+f"(d[2]), "+f"(d[3])
        : "r"(a[0]), "r"(a[1]), "r"(a[2]), "r"(a[3]), "r"(b[0]), "r"(b[1]));
}
__device__ __forceinline__ void ldsm4(u32* r, u32 addr) {
    asm volatile("ldmatrix.sync.aligned.m8n8.x4.shared.b16 {%0,%1,%2,%3}, [%4];"
                 : "=r"(r[0]), "=r"(r[1]), "=r"(r[2]), "=r"(r[3]) : "r"(addr));
}

// fp32x4 -> (hi bf16x4 @ addr, lo bf16x4 @ addr + LO_OFF bytes)
__device__ __forceinline__ void cvt_store(u32 addr_hi, u32 lo_off, float4 v) {
    u32 hp0, hp1;
    asm("cvt.rn.bf16x2.f32 %0, %1, %2;" : "=r"(hp0) : "f"(v.y), "f"(v.x));
    asm("cvt.rn.bf16x2.f32 %0, %1, %2;" : "=r"(hp1) : "f"(v.w), "f"(v.z));
    float r0 = v.x - __uint_as_float(hp0 << 16);
    float r1 = v.y - __uint_as_float(hp0 & 0xFFFF0000u);
    float r2 = v.z - __uint_as_float(hp1 << 16);
    float r3 = v.w - __uint_as_float(hp1 & 0xFFFF0000u);
    u32 lp0, lp1;
    asm("cvt.rn.bf16x2.f32 %0, %1, %2;" : "=r"(lp0) : "f"(r1), "f"(r0));
    asm("cvt.rn.bf16x2.f32 %0, %1, %2;" : "=r"(lp1) : "f"(r3), "f"(r2));
    asm volatile("st.shared.v2.b32 [%0], {%1, %2};" :: "r"(addr_hi), "r"(hp0), "r"(hp1));
    asm volatile("st.shared.v2.b32 [%0], {%1, %2};" :: "r"(addr_hi + lo_off), "r"(lp0), "r"(lp1));
}

// ============ tensor-core GEMM via mma.sync: C[8192, N] = A[8192,896] * W[N,896]^T (+bias) ============
// smem (halves, row stride 40 = 80B):
//   stage s at halfoff s*20480: Ahi[128*40] | Alo (+5120) | Bhi (+10240) | Blo (+15360)
#define RS 40                      // row stride in halves
#define STG_HALVES 20480
#define ABUF_LO_B  10240           // byte offset hi->lo
#define MMA_SMEM   (2 * STG_HALVES * 2)

template <int IS_O>
__global__ __launch_bounds__(256, 1)
void tc_gemm(const float* __restrict__ Ain,
             const float* __restrict__ W0, const float* __restrict__ b0,
             const float* __restrict__ W1, const float* __restrict__ b1,
             const float* __restrict__ W2, const float* __restrict__ b2,
             float* __restrict__ out)
{
    extern __shared__ char smraw[];
    const u32 smb = smem_u32(smraw);
    const int tid  = threadIdx.x;
    const int wid  = tid >> 5;
    const int lane = tid & 31;
    const int nb   = blockIdx.x;
    const int m0   = blockIdx.y * 128;

    const float* A = IS_O ? g_attn : Ain;

    const float* Wsel;
    const float* biasp = 0;
    float* dstbuf = 0;
    int nh = 0, ncol0 = 0;
    if (IS_O) {
        Wsel = W0 + (size_t)(nb * 128) * HID;
    } else {
        if (nb < 7)       { Wsel = W0 + (size_t)(nb * 128) * HID; biasp = b0; dstbuf = g_Q; nh = NH;  ncol0 = nb * 128; }
        else if (nb == 7) { Wsel = W1; biasp = b1; dstbuf = g_K; nh = NKV; ncol0 = 0; }
        else              { Wsel = W2; biasp = b2; dstbuf = g_V; nh = NKV; ncol0 = 0; }
    }

    const float* Asrc = A + (size_t)m0 * HID;

    // warp tiling: 2 (m) x 4 (n); warp tile 64x32
    const int wm = wid & 1;
    const int wn = wid >> 1;
    const int mbase = wm * 64;
    const int nbase = wn * 32;

    // gmem staging: thread loads 4 float4 of A and 4 of W per BK=32 chunk
    const int ldrow = tid >> 3;        // used with +64*f
    const int ldc4  = tid & 7;         // float4 col within 32-k chunk

    float4 aR[2][2], bR[2][2];         // [rowgrp][...]: rows ldrow, ldrow+32... (see below)
    // thread f-th float4: idx = tid + f*256 -> row = idx>>3 = ldrow + f*32
#define PRELOAD(it)                                                            \
    {                                                                          \
        const int kc0 = (it) * 32 + ldc4 * 4;                                  \
        _Pragma("unroll")                                                      \
        for (int f = 0; f < 2; ++f) {                                          \
            aR[f][0] = *(const float4*)(Asrc + (size_t)(ldrow + f * 64) * HID + kc0);       \
            aR[f][1] = *(const float4*)(Asrc + (size_t)(ldrow + f * 64 + 32) * HID + kc0);  \
            bR[f][0] = *(const float4*)(Wsel + (size_t)(ldrow + f * 64) * HID + kc0);       \
            bR[f][1] = *(const float4*)(Wsel + (size_t)(ldrow + f * 64 + 32) * HID + kc0);  \
        }                                                                      \
    }

    float acc[4][4][4];
#pragma unroll
    for (int i = 0; i < 4; ++i)
#pragma unroll
        for (int j = 0; j < 4; ++j)
#pragma unroll
            for (int k = 0; k < 4; ++k) acc[i][j][k] = 0.0f;

    PRELOAD(0);

    // ldmatrix address precompute (per lane), byte addresses rel. to buffer base
    const int g  = lane >> 3;
    const int l7 = lane & 7;
    // A frag: row = mbase + (g&1)*8 + l7 (+ mi*16), khalf = (g>>1)*8 (+ks)
    const u32 a_off = (u32)((mbase + (g & 1) * 8 + l7) * RS + (g >> 1) * 8) * 2;
    // B frag (x4 covers 2 n-blocks): row = nbase + (g>>1)*8 + l7 (+ jp*16), khalf = (g&1)*8 (+ks)
    const u32 b_off = (u32)((nbase + (g >> 1) * 8 + l7) * RS + (g & 1) * 8) * 2 + STG_HALVES * 0 + 10240 * 2;
    // note: B hi buffer at halfoff 10240 -> byte 20480; computed below explicitly

    for (int it = 0; it < 28; ++it) {
        const u32 stg = smb + (u32)(it & 1) * (STG_HALVES * 2);
        // store staged regs -> smem (hi + lo)
        {
            const u32 colb = (u32)(ldc4 * 4) * 2;   // byte offset of 4 halves
#pragma unroll
            for (int f = 0; f < 2; ++f) {
                const u32 rA0 = stg + (u32)((ldrow + f * 64) * RS) * 2 + colb;
                const u32 rA1 = stg + (u32)((ldrow + f * 64 + 32) * RS) * 2 + colb;
                cvt_store(rA0, ABUF_LO_B, aR[f][0]);
                cvt_store(rA1, ABUF_LO_B, aR[f][1]);
                const u32 rB0 = rA0 + 20480;   // Bhi at +10240 halves
                const u32 rB1 = rA1 + 20480;
                cvt_store(rB0, ABUF_LO_B, bR[f][0]);
                cvt_store(rB1, ABUF_LO_B, bR[f][1]);
            }
        }
        __syncthreads();
        if (it + 1 < 28) PRELOAD(it + 1);

#pragma unroll
        for (int ks = 0; ks < 2; ++ks) {
            const u32 kso = (u32)(ks * 16) * 2;
            u32 ahi[4][4], alo[4][4];
#pragma unroll
            for (int mi = 0; mi < 4; ++mi) {
                const u32 ad = stg + a_off + kso + (u32)(mi * 16 * RS) * 2;
                ldsm4(ahi[mi], ad);
                ldsm4(alo[mi], ad + ABUF_LO_B);
            }
            u32 bhi[4][2], blo[4][2];
#pragma unroll
            for (int jp = 0; jp < 2; ++jp) {
                const u32 bd = stg + 20480 + (u32)((nbase + (g >> 1) * 8 + l7 + jp * 16) * RS + (g & 1) * 8) * 2 + kso;
                u32 t4[4];
                ldsm4(t4, bd);
                bhi[2 * jp][0] = t4[0]; bhi[2 * jp][1] = t4[1];
                bhi[2 * jp + 1][0] = t4[2]; bhi[2 * jp + 1][1] = t4[3];
                ldsm4(t4, bd + ABUF_LO_B);
                blo[2 * jp][0] = t4[0]; blo[2 * jp][1] = t4[1];
                blo[2 * jp + 1][0] = t4[2]; blo[2 * jp + 1][1] = t4[3];
            }
#pragma unroll
            for (int mi = 0; mi < 4; ++mi)
#pragma unroll
                for (int nj = 0; nj < 4; ++nj) {
                    mma16816(acc[mi][nj], ahi[mi], bhi[nj]);
                    mma16816(acc[mi][nj], ahi[mi], blo[nj]);
                    mma16816(acc[mi][nj], alo[mi], bhi[nj]);
                }
        }
        __syncthreads();
    }

    // ---- epilogue: fragment layout -> gmem ----
    const int qrow = lane >> 2;
    const int qcol = (lane & 3) * 2;
#pragma unroll
    for (int mi = 0; mi < 4; ++mi) {
#pragma unroll
        for (int half = 0; half < 2; ++half) {
            const int r = mbase + mi * 16 + qrow + half * 8;
            const int m = m0 + r;
#pragma unroll
            for (int nj = 0; nj < 4; ++nj) {
                const int col = nbase + nj * 8 + qcol;
                const float v0 = acc[mi][nj][half * 2];
                const float v1 = acc[mi][nj][half * 2 + 1];
                if (IS_O) {
                    float* dst = out + (size_t)m * HID + nb * 128 + col;
                    float2 vv; vv.x = v0; vv.y = v1;
                    *(float2*)dst = vv;
                } else {
                    const int gc = ncol0 + col;
                    const int h  = gc >> 6;
                    const int d0 = gc & 63;
                    const int bb = m >> 11;
                    const int ss = m & (SLEN - 1);
                    float* dst = dstbuf + (((size_t)(bb * nh + h)) * SLEN + ss) * HD + d0;
                    float2 vv;
                    vv.x = v0 + biasp[gc];
                    vv.y = v1 + biasp[gc + 1];
                    *(float2*)dst = vv;
                }
            }
        }
    }
}

// ---------------- RoPE ----------------
__global__ void rope_kernel(const int* __restrict__ pos_ids) {
    const int QROWS = BATCH * NH * SLEN;
    const int idx  = blockIdx.x * blockDim.x + threadIdx.x;
    const int pair = idx & 31;
    const int row  = idx >> 5;

    float* base;
    if (row < QROWS) base = g_Q + (size_t)row * HD;
    else             base = g_K + (size_t)(row - QROWS) * HD;

    const int s   = row & (SLEN - 1);
    const float p = (float)pos_ids[s];
    const float ang = p * g_invf[pair];
    float sn, cs;
    sincosf(ang, &sn, &cs);
    const float x1 = base[pair];
    const float x2 = base[pair + 32];
    base[pair]      = x1 * cs - x2 * sn;
    base[pair + 32] = x2 * cs + x1 * sn;
}

// ---------------- Flash attention (causal, GQA) — FFMA2 version (unchanged) ----------------
#define FBM 128
#define FBN 128
#define QS_STRIDE 132
#define KS_STRIDE 132
#define VS_STRIDE 68
#define PS_STRIDE 132
#define FLASH_SMEM_FLOATS (64 * QS_STRIDE + 64 * KS_STRIDE + 128 * VS_STRIDE + 128 * PS_STRIDE)
#define FLASH_SMEM_BYTES  (FLASH_SMEM_FLOATS * 4)

__global__ __launch_bounds__(256, 1)
void flash_kernel() {
    extern __shared__ float sm[];
    float* Qs = sm;
    float* Ks = Qs + 64 * QS_STRIDE;
    float* Vs = Ks + 64 * KS_STRIDE;
    float* Ps = Vs + 128 * VS_STRIDE;

    const int tid = threadIdx.x;
    const int blk = blockIdx.x;
    const int h   = blockIdx.y;
    const int b   = blockIdx.z;
    const int qi0 = blk * FBM;
    const int kh  = h / NREP;

    const float* Qg  = g_Q + (((size_t)(b * NH + h)) * SLEN + qi0) * HD;
    const float* Kg0 = g_K + ((size_t)(b * NKV + kh)) * SLEN * HD;
    const float* Vg0 = g_V + ((size_t)(b * NKV + kh)) * SLEN * HD;

#pragma unroll
    for (int it = 0; it < 8; ++it) {
        const int idx = tid + it * 256;
        const int r   = idx >> 4;
        const int c4  = (idx & 15) << 2;
        const float4 v = *(const float4*)(Qg + (size_t)r * HD + c4);
        Qs[(c4 + 0) * QS_STRIDE + r] = v.x;
        Qs[(c4 + 1) * QS_STRIDE + r] = v.y;
        Qs[(c4 + 2) * QS_STRIDE + r] = v.z;
        Qs[(c4 + 3) * QS_STRIDE + r] = v.w;
    }

    const int ty = tid >> 4, tx = tid & 15;
    const int m0  = ty * 8;
    const int n0s = tx * 8;
    const int n0v = tx * 4;

    u64 o2[8][2];
    float l[8], mx[8];
#pragma unroll
    for (int i = 0; i < 8; ++i) {
        l[i] = 0.0f; mx[i] = -1e30f;
        o2[i][0] = 0ULL; o2[i][1] = 0ULL;
    }

    const float scale = 0.125f;
    const int jmax = blk;

    for (int j = 0; j <= jmax; ++j) {
        const int k0 = j * FBN;
        __syncthreads();

#pragma unroll
        for (int it = 0; it < 8; ++it) {
            const int idx = tid + it * 256;
            const int r   = idx >> 4;
            const int c4  = (idx & 15) << 2;
            const float4 kv = *(const float4*)(Kg0 + (size_t)(k0 + r) * HD + c4);
            Ks[(c4 + 0) * KS_STRIDE + r] = kv.x;
            Ks[(c4 + 1) * KS_STRIDE + r] = kv.y;
            Ks[(c4 + 2) * KS_STRIDE + r] = kv.z;
            Ks[(c4 + 3) * KS_STRIDE + r] = kv.w;
            const float4 vv = *(const float4*)(Vg0 + (size_t)(k0 + r) * HD + c4);
            *(float4*)&Vs[r * VS_STRIDE + c4] = vv;
        }
        __syncthreads();

        u64 sacc2[8][4];
#pragma unroll
        for (int i = 0; i < 8; ++i)
#pragma unroll
            for (int c = 0; c < 4; ++c) sacc2[i][c] = 0ULL;

#pragma unroll 4
        for (int d = 0; d < 64; ++d) {
            float af[8];
            *(float4*)&af[0] = *(const float4*)&Qs[d * QS_STRIDE + m0];
            *(float4*)&af[4] = *(const float4*)&Qs[d * QS_STRIDE + m0 + 4];
            const u64* bp = (const u64*)&Ks[d * KS_STRIDE + n0s];
            u64 b2[4];
            b2[0] = bp[0]; b2[1] = bp[1]; b2[2] = bp[2]; b2[3] = bp[3];
#pragma unroll
            for (int i = 0; i < 8; ++i) {
                u64 a2;
                PACKDUP(a2, __float_as_uint(af[i]));
                FFMA2(sacc2[i][0], a2, b2[0]);
                FFMA2(sacc2[i][1], a2, b2[1]);
                FFMA2(sacc2[i][2], a2, b2[2]);
                FFMA2(sacc2[i][3], a2, b2[3]);
            }
        }

        const bool need_mask = (j == blk);

#pragma unroll
        for (int i = 0; i < 8; ++i) {
            float s[8];
#pragma unroll
            for (int c = 0; c < 4; ++c) {
                unsigned int lo, hi;
                UNPACK2(lo, hi, sacc2[i][c]);
                s[2 * c]     = __uint_as_float(lo) * scale;
                s[2 * c + 1] = __uint_as_float(hi) * scale;
            }
            if (need_mask) {
#pragma unroll
                for (int c = 0; c < 8; ++c)
                    if (k0 + n0s + c > qi0 + m0 + i) s[c] = -1e30f;
            }

            float rm = s[0];
#pragma unroll
            for (int c = 1; c < 8; ++c) rm = fmaxf(rm, s[c]);
            rm = fmaxf(rm, __shfl_xor_sync(0xffffffffu, rm, 1));
            rm = fmaxf(rm, __shfl_xor_sync(0xffffffffu, rm, 2));
            rm = fmaxf(rm, __shfl_xor_sync(0xffffffffu, rm, 4));
            rm = fmaxf(rm, __shfl_xor_sync(0xffffffffu, rm, 8));

            const float mnew = fmaxf(mx[i], rm);
            const float corr = __expf(mx[i] - mnew);
            mx[i] = mnew;

            float rs = 0.0f;
#pragma unroll
            for (int c = 0; c < 8; ++c) {
                s[c] = __expf(s[c] - mnew);
                rs += s[c];
            }
            rs += __shfl_xor_sync(0xffffffffu, rs, 1);
            rs += __shfl_xor_sync(0xffffffffu, rs, 2);
            rs += __shfl_xor_sync(0xffffffffu, rs, 4);
            rs += __shfl_xor_sync(0xffffffffu, rs, 8);

            l[i] = l[i] * corr + rs;

            u64 c2;
            PACKDUP(c2, __float_as_uint(corr));
            FMUL2(o2[i][0], o2[i][0], c2);
            FMUL2(o2[i][1], o2[i][1], c2);

            *(float4*)&Ps[(m0 + i) * PS_STRIDE + n0s]     = *(float4*)&s[0];
            *(float4*)&Ps[(m0 + i) * PS_STRIDE + n0s + 4] = *(float4*)&s[4];
        }
        __syncthreads();

#pragma unroll 2
        for (int kk4 = 0; kk4 < 32; ++kk4) {
            const int kk = kk4 * 4;
            u64 v2[4][2];
#pragma unroll
            for (int q = 0; q < 4; ++q) {
                const u64* vp = (const u64*)&Vs[(kk + q) * VS_STRIDE + n0v];
                v2[q][0] = vp[0];
                v2[q][1] = vp[1];
            }
#pragma unroll
            for (int i = 0; i < 8; ++i) {
                float4 p4 = *(const float4*)&Ps[(m0 + i) * PS_STRIDE + kk];
                u64 p2;
                PACKDUP(p2, __float_as_uint(p4.x));
                FFMA2(o2[i][0], p2, v2[0][0]);
                FFMA2(o2[i][1], p2, v2[0][1]);
                PACKDUP(p2, __float_as_uint(p4.y));
                FFMA2(o2[i][0], p2, v2[1][0]);
                FFMA2(o2[i][1], p2, v2[1][1]);
                PACKDUP(p2, __float_as_uint(p4.z));
                FFMA2(o2[i][0], p2, v2[2][0]);
                FFMA2(o2[i][1], p2, v2[2][1]);
                PACKDUP(p2, __float_as_uint(p4.w));
                FFMA2(o2[i][0], p2, v2[3][0]);
                FFMA2(o2[i][1], p2, v2[3][1]);
            }
        }
    }

#pragma unroll
    for (int i = 0; i < 8; ++i) {
        const float invl = 1.0f / l[i];
        const int srow = qi0 + m0 + i;
        float* dst = g_attn + ((size_t)(b * SLEN) + srow) * (NH * HD) + h * HD + n0v;
        unsigned int lo, hi;
        float4 r;
        UNPACK2(lo, hi, o2[i][0]);
        r.x = __uint_as_float(lo) * invl; r.y = __uint_as_float(hi) * invl;
        UNPACK2(lo, hi, o2[i][1]);
        r.z = __uint_as_float(lo) * invl; r.w = __uint_as_float(hi) * invl;
        *(float4*)dst = r;
    }
}

// ---------------- launch ----------------
extern "C" void kernel_launch(void* const* d_in, const int* in_sizes, int n_in,
                              void* d_out, int out_size) {
    const float* hs  = (const float*)d_in[0];
    const int*   pos = (const int*)d_in[1];
    const float* Wq  = (const float*)d_in[2];
    const float* bq  = (const float*)d_in[3];
    const float* Wk  = (const float*)d_in[4];
    const float* bk  = (const float*)d_in[5];
    const float* Wv  = (const float*)d_in[6];
    const float* bv  = (const float*)d_in[7];
    const float* Wo  = (const float*)d_in[8];
    float* out = (float*)d_out;

    (void)in_sizes; (void)n_in; (void)out_size;

    cudaFuncSetAttribute(tc_gemm<0>, cudaFuncAttributeMaxDynamicSharedMemorySize, MMA_SMEM);
    cudaFuncSetAttribute(tc_gemm<1>, cudaFuncAttributeMaxDynamicSharedMemorySize, MMA_SMEM);
    cudaFuncSetAttribute(flash_kernel, cudaFuncAttributeMaxDynamicSharedMemorySize, FLASH_SMEM_BYTES);

    init_invf_kernel<<<1, 32>>>();

    // fused QKV projection on tensor cores (split-bf16, fp32-accurate)
    tc_gemm<0><<<dim3(9, 64), 256, MMA_SMEM>>>(hs, Wq, bq, Wk, bk, Wv, bv, nullptr);

    {
        const int qrows = BATCH * NH * SLEN;
        const int krows = BATCH * NKV * SLEN;
        const int total = (qrows + krows) * (HD / 2);
        rope_kernel<<<total / 256, 256>>>(pos);
    }

    flash_kernel<<<dim3(SLEN / FBM, NH, BATCH), 256, FLASH_SMEM_BYTES>>>();

    // O projection on tensor cores
    tc_gemm<1><<<dim3(7, 64), 256, MMA_SMEM>>>(nullptr, Wo, nullptr, nullptr, nullptr, nullptr, nullptr, out);
}

// round 7
// speedup vs baseline: 3.3019x; 2.0543x over previous
#include <cuda_runtime.h>
#include <cuda_bf16.h>
#include <math.h>

#define BATCH 4
#define SLEN  2048
#define HID   896
#define NH    14
#define NKV   2
#define HD    64
#define NREP  (NH / NKV)

typedef unsigned long long u64;
typedef unsigned int u32;

// ---------------- scratch ----------------
__device__ float g_Q[(size_t)BATCH * NH * SLEN * HD];    // [b][h][s][d]
__device__ float g_K[(size_t)BATCH * NKV * SLEN * HD];   // [b][kh][s][d]
__device__ float g_V[(size_t)BATCH * NKV * SLEN * HD];   // [b][kh][s][d]
__device__ float g_attn[(size_t)BATCH * SLEN * NH * HD]; // [b][s][h*HD+d]
__device__ float g_invf[HD / 2];

__global__ void init_invf_kernel() {
    int i = threadIdx.x;
    if (i < HD / 2) g_invf[i] = (float)pow(1.0e6, -(double)i / 32.0);
}

// ================= mma.sync helpers =================
__device__ __forceinline__ u32 smem_u32(const void* p) {
    u32 a;
    asm("{ .reg .u64 t; cvta.to.shared.u64 t, %1; cvt.u32.u64 %0, t; }" : "=r"(a) : "l"(p));
    return a;
}
__device__ __forceinline__ void mma16816(float* d, const u32* a, const u32* b) {
    asm volatile(
        "mma.sync.aligned.m16n8k16.row.col.f32.bf16.bf16.f32 "
        "{%0,%1,%2,%3}, {%4,%5,%6,%7}, {%8,%9}, {%0,%1,%2,%3};"
        : "+f"(d[0]), "+f"(d[1]), "+f"(d[2]), "+f"(d[3])
        : "r"(a[0]), "r"(a[1]), "r"(a[2]), "r"(a[3]), "r"(b[0]), "r"(b[1]));
}
__device__ __forceinline__ void ldsm4(u32* r, u32 addr) {
    asm volatile("ldmatrix.sync.aligned.m8n8.x4.shared.b16 {%0,%1,%2,%3}, [%4];"
                 : "=r"(r[0]), "=r"(r[1]), "=r"(r[2]), "=r"(r[3]) : "r"(addr));
}
__device__ __forceinline__ void ldsm4t(u32* r, u32 addr) {
    asm volatile("ldmatrix.sync.aligned.m8n8.x4.trans.shared.b16 {%0,%1,%2,%3}, [%4];"
                 : "=r"(r[0]), "=r"(r[1]), "=r"(r[2]), "=r"(r[3]) : "r"(addr));
}

// fp32x4 -> hi bf16x4 @ addr, residual-lo bf16x4 @ addr+lo_off
__device__ __forceinline__ void cvt_store(u32 addr_hi, u32 lo_off, float4 v) {
    u32 hp0, hp1;
    asm("cvt.rn.bf16x2.f32 %0, %1, %2;" : "=r"(hp0) : "f"(v.y), "f"(v.x));
    asm("cvt.rn.bf16x2.f32 %0, %1, %2;" : "=r"(hp1) : "f"(v.w), "f"(v.z));
    float r0 = v.x - __uint_as_float(hp0 << 16);
    float r1 = v.y - __uint_as_float(hp0 & 0xFFFF0000u);
    float r2 = v.z - __uint_as_float(hp1 << 16);
    float r3 = v.w - __uint_as_float(hp1 & 0xFFFF0000u);
    u32 lp0, lp1;
    asm("cvt.rn.bf16x2.f32 %0, %1, %2;" : "=r"(lp0) : "f"(r1), "f"(r0));
    asm("cvt.rn.bf16x2.f32 %0, %1, %2;" : "=r"(lp1) : "f"(r3), "f"(r2));
    asm volatile("st.shared.v2.b32 [%0], {%1, %2};" :: "r"(addr_hi), "r"(hp0), "r"(hp1));
    asm volatile("st.shared.v2.b32 [%0], {%1, %2};" :: "r"(addr_hi + lo_off), "r"(lp0), "r"(lp1));
}
// fp32 pair -> packed hi bf16x2 + residual bf16x2
__device__ __forceinline__ void split2(float x, float y, u32& hi, u32& lo) {
    asm("cvt.rn.bf16x2.f32 %0, %1, %2;" : "=r"(hi) : "f"(y), "f"(x));
    float rx = x - __uint_as_float(hi << 16);
    float ry = y - __uint_as_float(hi & 0xFFFF0000u);
    asm("cvt.rn.bf16x2.f32 %0, %1, %2;" : "=r"(lo) : "f"(ry), "f"(rx));
}

// ============ tensor-core GEMM (unchanged from R5) ============
#define RS 40
#define STG_HALVES 20480
#define ABUF_LO_B  10240
#define MMA_SMEM   (2 * STG_HALVES * 2)

template <int IS_O>
__global__ __launch_bounds__(256, 1)
void tc_gemm(const float* __restrict__ Ain,
             const float* __restrict__ W0, const float* __restrict__ b0,
             const float* __restrict__ W1, const float* __restrict__ b1,
             const float* __restrict__ W2, const float* __restrict__ b2,
             float* __restrict__ out)
{
    extern __shared__ char smraw[];
    const u32 smb = smem_u32(smraw);
    const int tid  = threadIdx.x;
    const int wid  = tid >> 5;
    const int lane = tid & 31;
    const int nb   = blockIdx.x;
    const int m0   = blockIdx.y * 128;

    const float* A = IS_O ? g_attn : Ain;

    const float* Wsel;
    const float* biasp = 0;
    float* dstbuf = 0;
    int nh = 0, ncol0 = 0;
    if (IS_O) {
        Wsel = W0 + (size_t)(nb * 128) * HID;
    } else {
        if (nb < 7)       { Wsel = W0 + (size_t)(nb * 128) * HID; biasp = b0; dstbuf = g_Q; nh = NH;  ncol0 = nb * 128; }
        else if (nb == 7) { Wsel = W1; biasp = b1; dstbuf = g_K; nh = NKV; ncol0 = 0; }
        else              { Wsel = W2; biasp = b2; dstbuf = g_V; nh = NKV; ncol0 = 0; }
    }

    const float* Asrc = A + (size_t)m0 * HID;

    const int wm = wid & 1;
    const int wn = wid >> 1;
    const int mbase = wm * 64;
    const int nbase = wn * 32;

    const int ldrow = tid >> 3;
    const int ldc4  = tid & 7;

    float4 aR[2][2], bR[2][2];
#define PRELOAD(it)                                                            \
    {                                                                          \
        const int kc0 = (it) * 32 + ldc4 * 4;                                  \
        _Pragma("unroll")                                                      \
        for (int f = 0; f < 2; ++f) {                                          \
            aR[f][0] = *(const float4*)(Asrc + (size_t)(ldrow + f * 64) * HID + kc0);       \
            aR[f][1] = *(const float4*)(Asrc + (size_t)(ldrow + f * 64 + 32) * HID + kc0);  \
            bR[f][0] = *(const float4*)(Wsel + (size_t)(ldrow + f * 64) * HID + kc0);       \
            bR[f][1] = *(const float4*)(Wsel + (size_t)(ldrow + f * 64 + 32) * HID + kc0);  \
        }                                                                      \
    }

    float acc[4][4][4];
#pragma unroll
    for (int i = 0; i < 4; ++i)
#pragma unroll
        for (int j = 0; j < 4; ++j)
#pragma unroll
            for (int k = 0; k < 4; ++k) acc[i][j][k] = 0.0f;

    PRELOAD(0);

    const int g  = lane >> 3;
    const int l7 = lane & 7;
    const u32 a_off = (u32)((mbase + (g & 1) * 8 + l7) * RS + (g >> 1) * 8) * 2;

    for (int it = 0; it < 28; ++it) {
        const u32 stg = smb + (u32)(it & 1) * (STG_HALVES * 2);
        {
            const u32 colb = (u32)(ldc4 * 4) * 2;
#pragma unroll
            for (int f = 0; f < 2; ++f) {
                const u32 rA0 = stg + (u32)((ldrow + f * 64) * RS) * 2 + colb;
                const u32 rA1 = stg + (u32)((ldrow + f * 64 + 32) * RS) * 2 + colb;
                cvt_store(rA0, ABUF_LO_B, aR[f][0]);
                cvt_store(rA1, ABUF_LO_B, aR[f][1]);
                cvt_store(rA0 + 20480, ABUF_LO_B, bR[f][0]);
                cvt_store(rA1 + 20480, ABUF_LO_B, bR[f][1]);
            }
        }
        __syncthreads();
        if (it + 1 < 28) PRELOAD(it + 1);

#pragma unroll
        for (int ks = 0; ks < 2; ++ks) {
            const u32 kso = (u32)(ks * 16) * 2;
            u32 ahi[4][4], alo[4][4];
#pragma unroll
            for (int mi = 0; mi < 4; ++mi) {
                const u32 ad = stg + a_off + kso + (u32)(mi * 16 * RS) * 2;
                ldsm4(ahi[mi], ad);
                ldsm4(alo[mi], ad + ABUF_LO_B);
            }
            u32 bhi[4][2], blo[4][2];
#pragma unroll
            for (int jp = 0; jp < 2; ++jp) {
                const u32 bd = stg + 20480 + (u32)((nbase + (g >> 1) * 8 + l7 + jp * 16) * RS + (g & 1) * 8) * 2 + kso;
                u32 t4[4];
                ldsm4(t4, bd);
                bhi[2 * jp][0] = t4[0]; bhi[2 * jp][1] = t4[1];
                bhi[2 * jp + 1][0] = t4[2]; bhi[2 * jp + 1][1] = t4[3];
                ldsm4(t4, bd + ABUF_LO_B);
                blo[2 * jp][0] = t4[0]; blo[2 * jp][1] = t4[1];
                blo[2 * jp + 1][0] = t4[2]; blo[2 * jp + 1][1] = t4[3];
            }
#pragma unroll
            for (int mi = 0; mi < 4; ++mi)
#pragma unroll
                for (int nj = 0; nj < 4; ++nj) {
                    mma16816(acc[mi][nj], ahi[mi], bhi[nj]);
                    mma16816(acc[mi][nj], ahi[mi], blo[nj]);
                    mma16816(acc[mi][nj], alo[mi], bhi[nj]);
                }
        }
        __syncthreads();
    }

    const int qrow = lane >> 2;
    const int qcol = (lane & 3) * 2;
#pragma unroll
    for (int mi = 0; mi < 4; ++mi) {
#pragma unroll
        for (int half = 0; half < 2; ++half) {
            const int r = mbase + mi * 16 + qrow + half * 8;
            const int m = m0 + r;
#pragma unroll
            for (int nj = 0; nj < 4; ++nj) {
                const int col = nbase + nj * 8 + qcol;
                const float v0 = acc[mi][nj][half * 2];
                const float v1 = acc[mi][nj][half * 2 + 1];
                if (IS_O) {
                    float* dst = out + (size_t)m * HID + nb * 128 + col;
                    float2 vv; vv.x = v0; vv.y = v1;
                    *(float2*)dst = vv;
                } else {
                    const int gc = ncol0 + col;
                    const int h  = gc >> 6;
                    const int d0 = gc & 63;
                    const int bb = m >> 11;
                    const int ss = m & (SLEN - 1);
                    float* dst = dstbuf + (((size_t)(bb * nh + h)) * SLEN + ss) * HD + d0;
                    float2 vv;
                    vv.x = v0 + biasp[gc];
                    vv.y = v1 + biasp[gc + 1];
                    *(float2*)dst = vv;
                }
            }
        }
    }
}

// ---------------- RoPE ----------------
__global__ void rope_kernel(const int* __restrict__ pos_ids) {
    const int QROWS = BATCH * NH * SLEN;
    const int idx  = blockIdx.x * blockDim.x + threadIdx.x;
    const int pair = idx & 31;
    const int row  = idx >> 5;

    float* base;
    if (row < QROWS) base = g_Q + (size_t)row * HD;
    else             base = g_K + (size_t)(row - QROWS) * HD;

    const int s   = row & (SLEN - 1);
    const float p = (float)pos_ids[s];
    const float ang = p * g_invf[pair];
    float sn, cs;
    sincosf(ang, &sn, &cs);
    const float x1 = base[pair];
    const float x2 = base[pair + 32];
    base[pair]      = x1 * cs - x2 * sn;
    base[pair + 32] = x2 * cs + x1 * sn;
}

// ---------------- Flash attention on tensor cores (causal, GQA) ----------------
// BM=128, BN=128, 8 warps; warp w owns q-rows [w*16, w*16+16).
// smem halves, row stride 72 (144B): Khi@0, Klo@18432, Vhi@36864, Vlo@55296 (bytes).
#define FRS 72
#define F_KH 0
#define F_LO 18432
#define F_VH 36864
#define FLASH_SMEM 73728

__global__ __launch_bounds__(256, 1)
void flash_mma() {
    extern __shared__ char smraw[];
    const u32 smb = smem_u32(smraw);
    const int tid  = threadIdx.x;
    const int wid  = tid >> 5;
    const int lane = tid & 31;

    const int blk = (int)gridDim.x - 1 - (int)blockIdx.x;  // heavy tiles first
    const int h   = blockIdx.y;
    const int b   = blockIdx.z;
    const int qi0 = blk * 128;
    const int kh  = h / NREP;

    const float* Qg  = g_Q + ((size_t)(b * NH + h)) * SLEN * HD;
    const float* Kg0 = g_K + ((size_t)(b * NKV + kh)) * SLEN * HD;
    const float* Vg0 = g_V + ((size_t)(b * NKV + kh)) * SLEN * HD;

    const int qr = lane >> 2;           // quad row
    const int q2 = (lane & 3) * 2;      // quad col pair
    const int row0 = qi0 + wid * 16 + qr;

    // ---- Q fragments in registers (scale 0.125 folded in; split hi/lo) ----
    u32 qhi[4][4], qlo[4][4];
#pragma unroll
    for (int kk = 0; kk < 4; ++kk) {
#pragma unroll
        for (int part = 0; part < 4; ++part) {
            const int r = row0 + (part & 1) * 8;
            const int c = kk * 16 + q2 + (part & 2) * 4;
            float2 v = *(const float2*)(Qg + (size_t)r * HD + c);
            split2(v.x * 0.125f, v.y * 0.125f, qhi[kk][part], qlo[kk][part]);
        }
    }

    float o[8][4];
#pragma unroll
    for (int i = 0; i < 8; ++i)
#pragma unroll
        for (int c = 0; c < 4; ++c) o[i][c] = 0.0f;
    float mx[2] = {-1e30f, -1e30f};
    float l[2]  = {0.0f, 0.0f};

    // ldmatrix lane address components
    const int l7 = lane & 7;
    const int n_add = l7 + ((lane >> 4) & 1) * 8;     // K (non-trans)
    const int k_add = ((lane >> 3) & 1) * 8;
    const int kv_add = l7 + ((lane >> 3) & 1) * 8;    // V (trans)
    const int dv_add = ((lane >> 4) & 1) * 8;

    for (int j = 0; j <= blk; ++j) {
        const int k0 = j * 128;
        __syncthreads();

        // load K,V tiles (fp32 -> split bf16 smem)
#pragma unroll
        for (int it = 0; it < 8; ++it) {
            const int idx = tid + it * 256;
            const int r   = idx >> 4;
            const int c4  = (idx & 15) << 2;
            const u32 soff = (u32)(r * FRS + c4) * 2;
            float4 kv = *(const float4*)(Kg0 + (size_t)(k0 + r) * HD + c4);
            cvt_store(smb + F_KH + soff, F_LO, kv);
            float4 vv = *(const float4*)(Vg0 + (size_t)(k0 + r) * HD + c4);
            cvt_store(smb + F_VH + soff, F_LO, vv);
        }
        __syncthreads();

        // ---- S = Q*K^T (split-bf16, 3 terms) ----
        float sacc[16][4];
#pragma unroll
        for (int i = 0; i < 16; ++i)
#pragma unroll
            for (int c = 0; c < 4; ++c) sacc[i][c] = 0.0f;

#pragma unroll
        for (int kk = 0; kk < 4; ++kk) {
#pragma unroll
            for (int nbp = 0; nbp < 8; ++nbp) {
                const u32 ad = smb + F_KH + (u32)((nbp * 16 + n_add) * FRS + kk * 16 + k_add) * 2;
                u32 kh4[4], kl4[4];
                ldsm4(kh4, ad);
                ldsm4(kl4, ad + F_LO);
                mma16816(sacc[2 * nbp],     qhi[kk], &kh4[0]);
                mma16816(sacc[2 * nbp],     qhi[kk], &kl4[0]);
                mma16816(sacc[2 * nbp],     qlo[kk], &kh4[0]);
                mma16816(sacc[2 * nbp + 1], qhi[kk], &kh4[2]);
                mma16816(sacc[2 * nbp + 1], qhi[kk], &kl4[2]);
                mma16816(sacc[2 * nbp + 1], qlo[kk], &kh4[2]);
            }
        }

        // ---- causal mask on diagonal tile ----
        if (j == blk) {
#pragma unroll
            for (int nb = 0; nb < 16; ++nb) {
                const int colb = k0 + nb * 8 + q2;
#pragma unroll
                for (int c = 0; c < 4; ++c) {
                    const int col = colb + (c & 1);
                    const int row = row0 + (c >> 1) * 8;
                    if (col > row) sacc[nb][c] = -1e30f;
                }
            }
        }

        // ---- online softmax (rows row0, row0+8) ----
#pragma unroll
        for (int hh = 0; hh < 2; ++hh) {
            float rm = -1e30f;
#pragma unroll
            for (int nb = 0; nb < 16; ++nb)
                rm = fmaxf(rm, fmaxf(sacc[nb][2 * hh], sacc[nb][2 * hh + 1]));
            rm = fmaxf(rm, __shfl_xor_sync(0xffffffffu, rm, 1));
            rm = fmaxf(rm, __shfl_xor_sync(0xffffffffu, rm, 2));

            const float mnew = fmaxf(mx[hh], rm);
            const float corr = __expf(mx[hh] - mnew);
            mx[hh] = mnew;

            float rs = 0.0f;
#pragma unroll
            for (int nb = 0; nb < 16; ++nb) {
                float p0 = __expf(sacc[nb][2 * hh] - mnew);
                float p1 = __expf(sacc[nb][2 * hh + 1] - mnew);
                sacc[nb][2 * hh] = p0;
                sacc[nb][2 * hh + 1] = p1;
                rs += p0 + p1;
            }
            rs += __shfl_xor_sync(0xffffffffu, rs, 1);
            rs += __shfl_xor_sync(0xffffffffu, rs, 2);
            l[hh] = l[hh] * corr + rs;
#pragma unroll
            for (int db = 0; db < 8; ++db) {
                o[db][2 * hh]     *= corr;
                o[db][2 * hh + 1] *= corr;
            }
        }

        // ---- pack P into A-fragments (hi + residual lo) ----
        u32 phi[8][4], plo[8][4];
#pragma unroll
        for (int kk = 0; kk < 8; ++kk) {
            split2(sacc[2 * kk][0],     sacc[2 * kk][1],     phi[kk][0], plo[kk][0]);
            split2(sacc[2 * kk][2],     sacc[2 * kk][3],     phi[kk][1], plo[kk][1]);
            split2(sacc[2 * kk + 1][0], sacc[2 * kk + 1][1], phi[kk][2], plo[kk][2]);
            split2(sacc[2 * kk + 1][2], sacc[2 * kk + 1][3], phi[kk][3], plo[kk][3]);
        }

        // ---- O += P*V (split-bf16, 3 terms) ----
#pragma unroll
        for (int kk = 0; kk < 8; ++kk) {
#pragma unroll
            for (int dbp = 0; dbp < 4; ++dbp) {
                const u32 ad = smb + F_VH + (u32)((kk * 16 + kv_add) * FRS + dbp * 16 + dv_add) * 2;
                u32 vh4[4], vl4[4];
                ldsm4t(vh4, ad);
                ldsm4t(vl4, ad + F_LO);
                mma16816(o[2 * dbp],     phi[kk], &vh4[0]);
                mma16816(o[2 * dbp],     phi[kk], &vl4[0]);
                mma16816(o[2 * dbp],     plo[kk], &vh4[0]);
                mma16816(o[2 * dbp + 1], phi[kk], &vh4[2]);
                mma16816(o[2 * dbp + 1], phi[kk], &vl4[2]);
                mma16816(o[2 * dbp + 1], plo[kk], &vh4[2]);
            }
        }
    }

    // ---- write O / l ----
#pragma unroll
    for (int hh = 0; hh < 2; ++hh) {
        const float inv = 1.0f / l[hh];
        const int row = row0 + hh * 8;
        float* dst = g_attn + ((size_t)(b * SLEN) + row) * (NH * HD) + h * HD;
#pragma unroll
        for (int db = 0; db < 8; ++db) {
            float2 v;
            v.x = o[db][2 * hh] * inv;
            v.y = o[db][2 * hh + 1] * inv;
            *(float2*)(dst + db * 8 + q2) = v;
        }
    }
}

// ---------------- launch ----------------
extern "C" void kernel_launch(void* const* d_in, const int* in_sizes, int n_in,
                              void* d_out, int out_size) {
    const float* hs  = (const float*)d_in[0];
    const int*   pos = (const int*)d_in[1];
    const float* Wq  = (const float*)d_in[2];
    const float* bq  = (const float*)d_in[3];
    const float* Wk  = (const float*)d_in[4];
    const float* bk  = (const float*)d_in[5];
    const float* Wv  = (const float*)d_in[6];
    const float* bv  = (const float*)d_in[7];
    const float* Wo  = (const float*)d_in[8];
    float* out = (float*)d_out;

    (void)in_sizes; (void)n_in; (void)out_size;

    cudaFuncSetAttribute(tc_gemm<0>, cudaFuncAttributeMaxDynamicSharedMemorySize, MMA_SMEM);
    cudaFuncSetAttribute(tc_gemm<1>, cudaFuncAttributeMaxDynamicSharedMemorySize, MMA_SMEM);
    cudaFuncSetAttribute(flash_mma, cudaFuncAttributeMaxDynamicSharedMemorySize, FLASH_SMEM);

    init_invf_kernel<<<1, 32>>>();

    tc_gemm<0><<<dim3(9, 64), 256, MMA_SMEM>>>(hs, Wq, bq, Wk, bk, Wv, bv, nullptr);

    {
        const int qrows = BATCH * NH * SLEN;
        const int krows = BATCH * NKV * SLEN;
        const int total = (qrows + krows) * (HD / 2);
        rope_kernel<<<total / 256, 256>>>(pos);
    }

    flash_mma<<<dim3(SLEN / 128, NH, BATCH), 256, FLASH_SMEM>>>();

    tc_gemm<1><<<dim3(7, 64), 256, MMA_SMEM>>>(nullptr, Wo, nullptr, nullptr, nullptr, nullptr, nullptr, out);
}